// round 13
// baseline (speedup 1.0000x reference)
#include <cuda_runtime.h>
#include <cuda_fp16.h>
#include <cstdint>

// ---------------------------------------------------------------------------
// MeshUpConv: 3x SplineConv (kernel 3x3, degree 2, open spline) on GB300.
//
// R12 -> R13: GEMM occupancy fix. MMA count proven non-binding (R12), so the
// mainloop is serialization-bound at 1 CTA/SM (110KB smem). Drop the W-lo
// piece -> plain fp16 MMA, smem 55KB:
//   * CTA = 256 thr, 64-row x 320-col tile, launch_bounds(256,2), grid 296
//     -> 2 CTAs/SM overlap staging/epilogue with compute (M-split: no
//     duplicated A staging, unlike the failed R8 N-split).
//   * Error: +W fp16 rounding (~1.4e-4 RMS) on message path -> ~3e-4 total.
// Edge pass (4 lanes/edge, uint4 fp16 gathers) + sort unchanged.
// ---------------------------------------------------------------------------

#define NMAX  50000
#define EMAX  400000
#define CKOUT 288          // K * C_OUT = 9 * 32
#define NCOLS 320          // 288 Y cols + 32 self cols

__device__ __half g_Y[(size_t)NMAX * CKOUT];
__device__ float  g_agg1[(size_t)NMAX * 32];
__device__ float  g_agg2[(size_t)NMAX * 32];

// sort scratch
__device__ int    g_hist[NMAX];
__device__ int    g_off[NMAX];
__device__ int    g_bsum[128];
__device__ int2   g_se[EMAX];     // sorted (src, dst)
__device__ float2 g_sp[EMAX];     // sorted pseudo

// ---- helpers --------------------------------------------------------------
__device__ __forceinline__ uint32_t pack_f16(float a, float b) {
    __half2 t = __floats2half2_rn(a, b);
    return *reinterpret_cast<uint32_t*>(&t);
}
__device__ __forceinline__ void mma_f16(float* c,
                                        uint32_t a0, uint32_t a1, uint32_t a2, uint32_t a3,
                                        uint32_t b0, uint32_t b1) {
    asm("mma.sync.aligned.m16n8k16.row.col.f32.f16.f16.f32 "
        "{%0,%1,%2,%3}, {%4,%5,%6,%7}, {%8,%9}, {%0,%1,%2,%3};"
        : "+f"(c[0]), "+f"(c[1]), "+f"(c[2]), "+f"(c[3])
        : "r"(a0), "r"(a1), "r"(a2), "r"(a3), "r"(b0), "r"(b1));
}
__device__ __forceinline__ void ldsm_x4(uint32_t& r0, uint32_t& r1,
                                        uint32_t& r2, uint32_t& r3, uint32_t a) {
    asm volatile("ldmatrix.sync.aligned.m8n8.x4.shared.b16 {%0,%1,%2,%3}, [%4];"
                 : "=r"(r0), "=r"(r1), "=r"(r2), "=r"(r3) : "r"(a));
}
__device__ __forceinline__ void ldsm_x2(uint32_t& r0, uint32_t& r1, uint32_t a) {
    asm volatile("ldmatrix.sync.aligned.m8n8.x2.shared.b16 {%0,%1}, [%2];"
                 : "=r"(r0), "=r"(r1) : "r"(a));
}
__device__ __forceinline__ uint32_t smem_addr(const void* p) {
    return (uint32_t)__cvta_generic_to_shared(p);
}

// SMEM layout. Stride 36 words: bank=(4q+r)%32 -> conflict-free fragments.
// A: 64 rows x 32 kpairs (fp16); B: 320 rows x 32 kpairs (fp16 single).
#define ASTR 36
#define SM_BIAS 0
#define SM_A    128
#define SM_B    (SM_A + 64 * ASTR * 4)           //  9344
#define SMEM_BYTES (SM_B + 320 * ASTR * 4)       // 55424

// ---------------------------------------------------------------------------
// mma.sync GEMM: CTA = 64-row x 320-col tile. 8 warps = 2(M) x 4(N);
// warp = 32 rows (2 mt) x 80 cols (10 nt). fp16 in, fp32 accum.
// ---------------------------------------------------------------------------
template<int CA, int CB, bool RELU_A, int CIN_W>
__global__ __launch_bounds__(256, 2)
void gemm_mma(const float* __restrict__ xa, const float* __restrict__ xb,
              const float* __restrict__ W, const float* __restrict__ root,
              const float* __restrict__ bias,
              __half* __restrict__ Y, float* __restrict__ agg, int n_nodes)
{
    extern __shared__ __align__(16) char smem[];
    uint32_t* Aa = reinterpret_cast<uint32_t*>(smem + SM_A);
    uint32_t* Bb = reinterpret_cast<uint32_t*>(smem + SM_B);
    float*    bs = reinterpret_cast<float*>(smem + SM_BIAS);

    const int tid    = threadIdx.x;
    const int wid    = tid >> 5;
    const int lane   = tid & 31;
    const int warp_m = wid >> 2;        // 0..1
    const int warp_n = wid & 3;         // 0..3
    constexpr int KSTEPS = CIN_W / 16;

    // ---- Stage B once per CTA (fp16; k padded to 64).
    for (int idx = tid; idx < NCOLS * 32; idx += 256) {
        const int r  = idx >> 5;
        const int kp = idx & 31;
        const int i0 = 2 * kp, i1 = i0 + 1;
        float v0 = 0.0f, v1 = 0.0f;
        if (i0 < CIN_W) {
            if (r < CKOUT) {
                const int kk = r >> 5, cc = r & 31;
                v0 = W[(kk * CIN_W + i0) * 32 + cc];
                v1 = W[(kk * CIN_W + i1) * 32 + cc];
            } else {
                v0 = root[i0 * 32 + (r - CKOUT)];
                v1 = root[i1 * 32 + (r - CKOUT)];
            }
        }
        Bb[r * ASTR + kp] = pack_f16(v0, v1);
    }
    if (tid < 32) bs[tid] = bias[tid];
    __syncthreads();

    const uint32_t aoffw = (uint32_t)(warp_m * 32 + (lane & 15)) * ASTR + (lane >> 4) * 4;
    const uint32_t boffw = (uint32_t)(warp_n * 80 + (lane & 7)) * ASTR + ((lane >> 3) & 1) * 4;
    const uint32_t aA = smem_addr(Aa) + 4 * aoffw;
    const uint32_t bB = smem_addr(Bb) + 4 * boffw;

    const int ntiles = (n_nodes + 63) >> 6;

    for (int t = blockIdx.x; t < ntiles; t += gridDim.x) {
        const int n0 = t << 6;

        // ---- Stage A tile: 64 rows x 32 k-pairs (relu/concat fused).
        for (int idx = tid; idx < 64 * 32; idx += 256) {
            const int row = idx >> 5;
            const int kp  = idx & 31;
            const int n   = n0 + row;
            const int i0  = 2 * kp, i1 = i0 + 1;
            float v0 = 0.0f, v1 = 0.0f;
            if (n < n_nodes) {
                if (i0 < CA) {
                    v0 = xa[(size_t)n * CA + i0];
                    v1 = xa[(size_t)n * CA + i1];
                    if (RELU_A) { v0 = fmaxf(v0, 0.0f); v1 = fmaxf(v1, 0.0f); }
                } else if (CB > 0 && i0 < CA + CB) {
                    v0 = xb[(size_t)n * CB + (i0 - CA)];
                    v1 = xb[(size_t)n * CB + (i1 - CA)];
                }
            }
            Aa[row * ASTR + kp] = pack_f16(v0, v1);
        }
        __syncthreads();

        float acc[2][10][4];
        #pragma unroll
        for (int mt = 0; mt < 2; mt++)
            #pragma unroll
            for (int nt = 0; nt < 10; nt++)
                #pragma unroll
                for (int j = 0; j < 4; j++) acc[mt][nt][j] = 0.0f;

        #pragma unroll
        for (int ks = 0; ks < KSTEPS; ks++) {
            const uint32_t ko = 4u * ks * 8;
            uint32_t a_[2][4];
            #pragma unroll
            for (int mt = 0; mt < 2; mt++) {
                const uint32_t mo = 4u * (warp_m * 32 + mt * 16 - (warp_m * 32)) * ASTR; // mt*16 rows
                ldsm_x4(a_[mt][0], a_[mt][1], a_[mt][2], a_[mt][3],
                        aA + 4u * mt * 16 * ASTR + ko);
                (void)mo;
            }
            #pragma unroll
            for (int nt = 0; nt < 10; nt++) {
                uint32_t b0, b1;
                ldsm_x2(b0, b1, bB + 4u * nt * 8 * ASTR + ko);
                #pragma unroll
                for (int mt = 0; mt < 2; mt++)
                    mma_f16(acc[mt][nt], a_[mt][0], a_[mt][1], a_[mt][2], a_[mt][3], b0, b1);
            }
        }

        // ---- Epilogue: Y cols -> fp16 (half2); self cols -> fp32 agg.
        const int q   = lane >> 2;
        const int lkp = lane & 3;
        #pragma unroll
        for (int mt = 0; mt < 2; mt++) {
            const int r0 = n0 + warp_m * 32 + mt * 16 + q;
            const int r1 = r0 + 8;
            #pragma unroll
            for (int nt = 0; nt < 10; nt++) {
                const int col0 = warp_n * 80 + nt * 8 + 2 * lkp;
                if (col0 < CKOUT) {
                    if (r0 < n_nodes)
                        *reinterpret_cast<__half2*>(Y + (size_t)r0 * CKOUT + col0)
                            = __floats2half2_rn(acc[mt][nt][0], acc[mt][nt][1]);
                    if (r1 < n_nodes)
                        *reinterpret_cast<__half2*>(Y + (size_t)r1 * CKOUT + col0)
                            = __floats2half2_rn(acc[mt][nt][2], acc[mt][nt][3]);
                } else {
                    const int a = col0 - CKOUT;
                    const float b0v = bs[a], b1v = bs[a + 1];
                    if (r0 < n_nodes)
                        *reinterpret_cast<float2*>(agg + (size_t)r0 * 32 + a)
                            = make_float2(acc[mt][nt][0] + b0v, acc[mt][nt][1] + b1v);
                    if (r1 < n_nodes)
                        *reinterpret_cast<float2*>(agg + (size_t)r1 * 32 + a)
                            = make_float2(acc[mt][nt][2] + b0v, acc[mt][nt][3] + b1v);
                }
            }
        }
        __syncthreads();
    }
}

// ---------------------------------------------------------------------------
// Counting sort of edges by src (once per launch, reused by 3 edge passes).
// ---------------------------------------------------------------------------
__global__ void hist_zero(int n) {
    const int i = blockIdx.x * blockDim.x + threadIdx.x;
    if (i < n) g_hist[i] = 0;
}
__global__ void hist_kernel(const int* __restrict__ ei, int n_edges) {
    const int e = blockIdx.x * blockDim.x + threadIdx.x;
    if (e < n_edges) atomicAdd(&g_hist[ei[e]], 1);
}
__global__ void scan1(int n) {
    __shared__ int s[512];
    const int tid = threadIdx.x;
    const int b   = blockIdx.x * 512 + tid;
    const int v   = (b < n) ? g_hist[b] : 0;
    s[tid] = v;
    __syncthreads();
    #pragma unroll
    for (int off = 1; off < 512; off <<= 1) {
        int t = (tid >= off) ? s[tid - off] : 0;
        __syncthreads();
        s[tid] += t;
        __syncthreads();
    }
    if (b < n) g_off[b] = s[tid] - v;
    if (tid == 511) g_bsum[blockIdx.x] = s[511];
}
__global__ void scan3(int n) {
    __shared__ int pref;
    const int bid = blockIdx.x;
    if (threadIdx.x < 32) {
        int s = 0;
        for (int i = threadIdx.x; i < bid; i += 32) s += g_bsum[i];
        #pragma unroll
        for (int o = 16; o; o >>= 1) s += __shfl_down_sync(0xffffffffu, s, o);
        if (threadIdx.x == 0) pref = s;
    }
    __syncthreads();
    const int b = bid * 512 + threadIdx.x;
    if (b < n) g_off[b] += pref;
}
__global__ void scatter_kernel(const int* __restrict__ ei,
                               const float* __restrict__ pseudo, int n_edges) {
    const int e = blockIdx.x * blockDim.x + threadIdx.x;
    if (e >= n_edges) return;
    const int src = ei[e];
    const int dst = ei[n_edges + e];
    const int pos = atomicAdd(&g_off[src], 1);
    g_se[pos] = make_int2(src, dst);
    g_sp[pos] = reinterpret_cast<const float2*>(pseudo)[e];
}

// ---------------------------------------------------------------------------
// Edge kernel (sorted by src): 4 lanes/edge, 8 channels/lane.
// Per lane: 9 x LDG.128 (uint4 = 8 fp16) + 2 x red.v4.f32.
// ---------------------------------------------------------------------------
__global__ __launch_bounds__(256)
void edge_kernel(const __half* __restrict__ Y, float* __restrict__ agg,
                 int n_edges, int n_nodes)
{
    const int t   = blockIdx.x * 256 + threadIdx.x;
    const int e   = t >> 2;
    const int sub = t & 3;            // channels [8*sub, 8*sub+8)
    if (e >= n_edges) return;

    const int2   sd = g_se[e];
    const float2 p  = g_sp[e];
    if ((unsigned)sd.x >= (unsigned)n_nodes || (unsigned)sd.y >= (unsigned)n_nodes) return;

    const float q00 = 0.5f * (1.0f - p.x) * (1.0f - p.x);
    const float q01 = -p.x * p.x + p.x + 0.5f;
    const float q02 = 0.5f * p.x * p.x;
    const float q10 = 0.5f * (1.0f - p.y) * (1.0f - p.y);
    const float q11 = -p.y * p.y + p.y + 0.5f;
    const float q12 = 0.5f * p.y * p.y;

    const float bb[9] = { q10*q00, q10*q01, q10*q02,
                          q11*q00, q11*q01, q11*q02,
                          q12*q00, q12*q01, q12*q02 };

    const uint4* y = reinterpret_cast<const uint4*>(Y + (size_t)sd.x * CKOUT + sub * 8);

    float acc[8] = {0,0,0,0,0,0,0,0};
    #pragma unroll
    for (int k = 0; k < 9; k++) {
        const uint4 qv = y[k * 4];
        const float bk = bb[k];
        const float2 f0 = __half22float2(*reinterpret_cast<const __half2*>(&qv.x));
        const float2 f1 = __half22float2(*reinterpret_cast<const __half2*>(&qv.y));
        const float2 f2 = __half22float2(*reinterpret_cast<const __half2*>(&qv.z));
        const float2 f3 = __half22float2(*reinterpret_cast<const __half2*>(&qv.w));
        acc[0] += bk * f0.x; acc[1] += bk * f0.y;
        acc[2] += bk * f1.x; acc[3] += bk * f1.y;
        acc[4] += bk * f2.x; acc[5] += bk * f2.y;
        acc[6] += bk * f3.x; acc[7] += bk * f3.y;
    }

    float* dp = agg + (size_t)sd.y * 32 + sub * 8;
    asm volatile("red.global.add.v4.f32 [%0], {%1, %2, %3, %4};"
                 :: "l"(dp), "f"(acc[0]), "f"(acc[1]), "f"(acc[2]), "f"(acc[3]) : "memory");
    asm volatile("red.global.add.v4.f32 [%0], {%1, %2, %3, %4};"
                 :: "l"(dp + 4), "f"(acc[4]), "f"(acc[5]), "f"(acc[6]), "f"(acc[7]) : "memory");
}

__global__ void relu_kernel(float* __restrict__ d, int n)
{
    const int i = blockIdx.x * blockDim.x + threadIdx.x;
    if (i < n) d[i] = fmaxf(d[i], 0.0f);
}

// ---------------------------------------------------------------------------
extern "C" void kernel_launch(void* const* d_in, const int* in_sizes, int n_in,
                              void* d_out, int out_size)
{
    const float* x      = (const float*)d_in[0];
    const int*   ei     = (const int*)d_in[1];     // int64 in ref -> int32 in harness
    const float* pseudo = (const float*)d_in[2];
    const float* skip   = (const float*)d_in[3];
    const float* W1     = (const float*)d_in[4];
    const float* root1  = (const float*)d_in[5];
    const float* b1     = (const float*)d_in[6];
    const float* W2     = (const float*)d_in[7];
    const float* root2  = (const float*)d_in[8];
    const float* b2     = (const float*)d_in[9];

    const int N = in_sizes[0] / 64;
    const int E = in_sizes[1] / 2;
    float* out = (float*)d_out;

    __half* Y;
    float *agg1, *agg2;
    cudaGetSymbolAddress((void**)&Y,    g_Y);
    cudaGetSymbolAddress((void**)&agg1, g_agg1);
    cudaGetSymbolAddress((void**)&agg2, g_agg2);

    cudaFuncSetAttribute(gemm_mma<64, 0,  false, 64>,
                         cudaFuncAttributeMaxDynamicSharedMemorySize, SMEM_BYTES);
    cudaFuncSetAttribute(gemm_mma<32, 32, true,  64>,
                         cudaFuncAttributeMaxDynamicSharedMemorySize, SMEM_BYTES);
    cudaFuncSetAttribute(gemm_mma<32, 0,  true,  32>,
                         cudaFuncAttributeMaxDynamicSharedMemorySize, SMEM_BYTES);

    const int gemm_grid = 296;          // 2 CTAs/SM
    const int edge_grid = (E * 4 + 255) / 256;
    const int NB        = (N + 511) / 512;

    // ---- Sort edges by src (once; reused by all 3 edge passes).
    hist_zero<<<NB, 512>>>(N);
    hist_kernel<<<(E + 255) / 256, 256>>>(ei, E);
    scan1<<<NB, 512>>>(N);
    scan3<<<NB, 512>>>(N);
    scatter_kernel<<<(E + 255) / 256, 256>>>(ei, pseudo, E);

    // Layer 1: x[N,64] -> agg1
    gemm_mma<64, 0, false, 64><<<gemm_grid, 256, SMEM_BYTES>>>(x, nullptr, W1, root1, b1, Y, agg1, N);
    edge_kernel<<<edge_grid, 256>>>(Y, agg1, E, N);

    // Layer 2: concat(relu(agg1), skip)[N,64] -> agg2   (same W1/root1/b1)
    gemm_mma<32, 32, true, 64><<<gemm_grid, 256, SMEM_BYTES>>>(agg1, skip, W1, root1, b1, Y, agg2, N);
    edge_kernel<<<edge_grid, 256>>>(Y, agg2, E, N);

    // Layer 3: relu(agg2)[N,32] -> d_out  (K = 32 -> 2 k-steps)
    gemm_mma<32, 0, true, 32><<<gemm_grid, 256, SMEM_BYTES>>>(agg2, nullptr, W2, root2, b2, Y, out, N);
    edge_kernel<<<edge_grid, 256>>>(Y, out, E, N);

    relu_kernel<<<(N * 32 + 255) / 256, 256>>>(out, N * 32);
}

// round 14
// speedup vs baseline: 1.1291x; 1.1291x over previous
#include <cuda_runtime.h>
#include <cuda_fp16.h>
#include <cstdint>

// ---------------------------------------------------------------------------
// MeshUpConv: 3x SplineConv (kernel 3x3, degree 2, open spline) on GB300.
//
// R13 -> R14: revert to R12 geometry (128x320 tile, grid 148, fp16 A +
// fp16 hi/lo W, 2 MMAs). NEW:
//   * A-staging register double-buffer: next tile's 8x LDG.64/thread issued
//     before the MMA loop (latency hidden under 160 MMAs); convert+STS at
//     the top of the next iteration.
//   * hist_zero launch replaced by cudaMemsetAsync (graph-legal).
// Edge pass (4 lanes/edge, uint4 fp16 gathers) + sort otherwise unchanged.
// ---------------------------------------------------------------------------

#define NMAX  50000
#define EMAX  400000
#define CKOUT 288          // K * C_OUT = 9 * 32
#define NCOLS 320          // 288 Y cols + 32 self cols

__device__ __half g_Y[(size_t)NMAX * CKOUT];
__device__ float  g_agg1[(size_t)NMAX * 32];
__device__ float  g_agg2[(size_t)NMAX * 32];

// sort scratch
__device__ int    g_hist[NMAX];
__device__ int    g_off[NMAX];
__device__ int    g_bsum[128];
__device__ int2   g_se[EMAX];     // sorted (src, dst)
__device__ float2 g_sp[EMAX];     // sorted pseudo

// ---- helpers --------------------------------------------------------------
__device__ __forceinline__ uint32_t pack_f16(float a, float b) {
    __half2 t = __floats2half2_rn(a, b);
    return *reinterpret_cast<uint32_t*>(&t);
}
__device__ __forceinline__ void mma_f16(float* c,
                                        uint32_t a0, uint32_t a1, uint32_t a2, uint32_t a3,
                                        uint32_t b0, uint32_t b1) {
    asm("mma.sync.aligned.m16n8k16.row.col.f32.f16.f16.f32 "
        "{%0,%1,%2,%3}, {%4,%5,%6,%7}, {%8,%9}, {%0,%1,%2,%3};"
        : "+f"(c[0]), "+f"(c[1]), "+f"(c[2]), "+f"(c[3])
        : "r"(a0), "r"(a1), "r"(a2), "r"(a3), "r"(b0), "r"(b1));
}
__device__ __forceinline__ void ldsm_x4(uint32_t& r0, uint32_t& r1,
                                        uint32_t& r2, uint32_t& r3, uint32_t a) {
    asm volatile("ldmatrix.sync.aligned.m8n8.x4.shared.b16 {%0,%1,%2,%3}, [%4];"
                 : "=r"(r0), "=r"(r1), "=r"(r2), "=r"(r3) : "r"(a));
}
__device__ __forceinline__ void ldsm_x2(uint32_t& r0, uint32_t& r1, uint32_t a) {
    asm volatile("ldmatrix.sync.aligned.m8n8.x2.shared.b16 {%0,%1}, [%2];"
                 : "=r"(r0), "=r"(r1) : "r"(a));
}
__device__ __forceinline__ uint32_t smem_addr(const void* p) {
    return (uint32_t)__cvta_generic_to_shared(p);
}

// SMEM layout. Stride 36 words: bank=(4q+r)%32 -> conflict-free fragments.
// A: 128 rows x 32 kpairs (fp16 single); B: 320 rows x 32 kpairs, hi & lo.
#define ASTR 36
#define SM_BIAS 0
#define SM_A    128
#define SM_B_HI (SM_A + 128 * ASTR * 4)          // 18560
#define SM_B_LO (SM_B_HI + 320 * ASTR * 4)       // 64640
#define SMEM_BYTES (SM_B_LO + 320 * ASTR * 4)    // 110720

// ---------------------------------------------------------------------------
// mma.sync GEMM: per 128-node tile, D[128, 320] = A[128,64] @ Bw[64,320].
// 16 warps = 4(M) x 4(N); warp = 32 rows x 80 cols. fp16 A, fp16x2 W, fp32 acc.
// A staging double-buffered through registers (prefetch overlaps MMA loop).
// ---------------------------------------------------------------------------
template<int CA, int CB, bool RELU_A, int CIN_W>
__global__ __launch_bounds__(512)
void gemm_mma(const float* __restrict__ xa, const float* __restrict__ xb,
              const float* __restrict__ W, const float* __restrict__ root,
              const float* __restrict__ bias,
              __half* __restrict__ Y, float* __restrict__ agg, int n_nodes)
{
    extern __shared__ __align__(16) char smem[];
    uint32_t* Aa = reinterpret_cast<uint32_t*>(smem + SM_A);
    uint32_t* Bh = reinterpret_cast<uint32_t*>(smem + SM_B_HI);
    uint32_t* Bl = reinterpret_cast<uint32_t*>(smem + SM_B_LO);
    float*    bs = reinterpret_cast<float*>(smem + SM_BIAS);

    const int tid    = threadIdx.x;
    const int wid    = tid >> 5;
    const int lane   = tid & 31;
    const int warp_m = wid >> 2;
    const int warp_n = wid & 3;
    constexpr int KSTEPS = CIN_W / 16;

    // ---- Stage B once per CTA: W split into fp16 hi + lo (exact).
    for (int idx = tid; idx < NCOLS * 32; idx += 512) {
        const int r  = idx >> 5;
        const int kp = idx & 31;
        const int i0 = 2 * kp, i1 = i0 + 1;
        float v0 = 0.0f, v1 = 0.0f;
        if (i0 < CIN_W) {
            if (r < CKOUT) {
                const int kk = r >> 5, cc = r & 31;
                v0 = W[(kk * CIN_W + i0) * 32 + cc];
                v1 = W[(kk * CIN_W + i1) * 32 + cc];
            } else {
                v0 = root[i0 * 32 + (r - CKOUT)];
                v1 = root[i1 * 32 + (r - CKOUT)];
            }
        }
        const float h0 = __half2float(__float2half_rn(v0));
        const float h1 = __half2float(__float2half_rn(v1));
        Bh[r * ASTR + kp] = pack_f16(h0, h1);
        Bl[r * ASTR + kp] = pack_f16(v0 - h0, v1 - h1);
    }
    if (tid < 32) bs[tid] = bias[tid];

    const uint32_t aoffw = (uint32_t)(warp_m * 32 + (lane & 15)) * ASTR + (lane >> 4) * 4;
    const uint32_t boffw = (uint32_t)(warp_n * 80 + (lane & 7)) * ASTR + ((lane >> 3) & 1) * 4;
    const uint32_t aA = smem_addr(Aa) + 4 * aoffw;
    const uint32_t bH = smem_addr(Bh) + 4 * boffw;
    const uint32_t bL = smem_addr(Bl) + 4 * boffw;

    const int ntiles = (n_nodes + 127) >> 7;

    // Per-thread A-staging slots: idx = tid + k*512, k = 0..7.
    // row = idx>>5, kp = idx&31; source = float2 at channel 2*kp.
    auto load_tile = [&](int t, float2* pf) {
        const int n0 = t << 7;
        #pragma unroll
        for (int k = 0; k < 8; k++) {
            const int idx = tid + k * 512;
            const int row = idx >> 5;
            const int kp  = idx & 31;
            const int n   = n0 + row;
            const int i0  = 2 * kp;
            float2 v = make_float2(0.0f, 0.0f);
            if (n < n_nodes) {
                if (i0 < CA) {
                    v = *reinterpret_cast<const float2*>(xa + (size_t)n * CA + i0);
                } else if (CB > 0 && i0 < CA + CB) {
                    v = *reinterpret_cast<const float2*>(xb + (size_t)n * CB + (i0 - CA));
                }
            }
            pf[k] = v;
        }
    };

    int t = blockIdx.x;
    float2 pf[8];
    if (t < ntiles) load_tile(t, pf);
    __syncthreads();   // B ready (and A buffer free)

    for (; t < ntiles; t += gridDim.x) {
        const int n0 = t << 7;

        // ---- STS the prefetched tile (relu fused here).
        #pragma unroll
        for (int k = 0; k < 8; k++) {
            const int idx = tid + k * 512;
            const int row = idx >> 5;
            const int kp  = idx & 31;
            float v0 = pf[k].x, v1 = pf[k].y;
            if (RELU_A) {
                const int i0 = 2 * kp;
                if (i0 < CA) { v0 = fmaxf(v0, 0.0f); v1 = fmaxf(v1, 0.0f); }
            }
            Aa[row * ASTR + kp] = pack_f16(v0, v1);
        }
        __syncthreads();

        // ---- Prefetch next tile (latency hidden under the MMA loop).
        const int tn = t + gridDim.x;
        if (tn < ntiles) load_tile(tn, pf);

        float acc[2][10][4];
        #pragma unroll
        for (int mt = 0; mt < 2; mt++)
            #pragma unroll
            for (int nt = 0; nt < 10; nt++)
                #pragma unroll
                for (int j = 0; j < 4; j++) acc[mt][nt][j] = 0.0f;

        #pragma unroll
        for (int ks = 0; ks < KSTEPS; ks++) {
            const uint32_t ko = 4u * ks * 8;
            uint32_t a_[2][4];
            #pragma unroll
            for (int mt = 0; mt < 2; mt++)
                ldsm_x4(a_[mt][0], a_[mt][1], a_[mt][2], a_[mt][3],
                        aA + 4u * mt * 16 * ASTR + ko);
            #pragma unroll
            for (int nt = 0; nt < 10; nt++) {
                const uint32_t no = 4u * nt * 8 * ASTR;
                uint32_t bh0, bh1, bl0, bl1;
                ldsm_x2(bh0, bh1, bH + no + ko);
                ldsm_x2(bl0, bl1, bL + no + ko);
                #pragma unroll
                for (int mt = 0; mt < 2; mt++) {
                    mma_f16(acc[mt][nt], a_[mt][0], a_[mt][1], a_[mt][2], a_[mt][3], bh0, bh1);
                    mma_f16(acc[mt][nt], a_[mt][0], a_[mt][1], a_[mt][2], a_[mt][3], bl0, bl1);
                }
            }
        }

        // ---- Epilogue: Y cols -> fp16 (half2 store); self cols -> fp32 agg.
        const int q   = lane >> 2;
        const int lkp = lane & 3;
        #pragma unroll
        for (int mt = 0; mt < 2; mt++) {
            const int r0 = n0 + warp_m * 32 + mt * 16 + q;
            const int r1 = r0 + 8;
            #pragma unroll
            for (int nt = 0; nt < 10; nt++) {
                const int col0 = warp_n * 80 + nt * 8 + 2 * lkp;
                if (col0 < CKOUT) {
                    if (r0 < n_nodes)
                        *reinterpret_cast<__half2*>(Y + (size_t)r0 * CKOUT + col0)
                            = __floats2half2_rn(acc[mt][nt][0], acc[mt][nt][1]);
                    if (r1 < n_nodes)
                        *reinterpret_cast<__half2*>(Y + (size_t)r1 * CKOUT + col0)
                            = __floats2half2_rn(acc[mt][nt][2], acc[mt][nt][3]);
                } else {
                    const int a = col0 - CKOUT;
                    const float b0v = bs[a], b1v = bs[a + 1];
                    if (r0 < n_nodes)
                        *reinterpret_cast<float2*>(agg + (size_t)r0 * 32 + a)
                            = make_float2(acc[mt][nt][0] + b0v, acc[mt][nt][1] + b1v);
                    if (r1 < n_nodes)
                        *reinterpret_cast<float2*>(agg + (size_t)r1 * 32 + a)
                            = make_float2(acc[mt][nt][2] + b0v, acc[mt][nt][3] + b1v);
                }
            }
        }
        __syncthreads();   // done reading Aa before next STS
    }
}

// ---------------------------------------------------------------------------
// Counting sort of edges by src (once per launch, reused by 3 edge passes).
// ---------------------------------------------------------------------------
__global__ void hist_kernel(const int* __restrict__ ei, int n_edges) {
    const int e = blockIdx.x * blockDim.x + threadIdx.x;
    if (e < n_edges) atomicAdd(&g_hist[ei[e]], 1);
}
__global__ void scan1(int n) {
    __shared__ int s[512];
    const int tid = threadIdx.x;
    const int b   = blockIdx.x * 512 + tid;
    const int v   = (b < n) ? g_hist[b] : 0;
    s[tid] = v;
    __syncthreads();
    #pragma unroll
    for (int off = 1; off < 512; off <<= 1) {
        int t = (tid >= off) ? s[tid - off] : 0;
        __syncthreads();
        s[tid] += t;
        __syncthreads();
    }
    if (b < n) g_off[b] = s[tid] - v;
    if (tid == 511) g_bsum[blockIdx.x] = s[511];
}
__global__ void scan3(int n) {
    __shared__ int pref;
    const int bid = blockIdx.x;
    if (threadIdx.x < 32) {
        int s = 0;
        for (int i = threadIdx.x; i < bid; i += 32) s += g_bsum[i];
        #pragma unroll
        for (int o = 16; o; o >>= 1) s += __shfl_down_sync(0xffffffffu, s, o);
        if (threadIdx.x == 0) pref = s;
    }
    __syncthreads();
    const int b = bid * 512 + threadIdx.x;
    if (b < n) g_off[b] += pref;
}
__global__ void scatter_kernel(const int* __restrict__ ei,
                               const float* __restrict__ pseudo, int n_edges) {
    const int e = blockIdx.x * blockDim.x + threadIdx.x;
    if (e >= n_edges) return;
    const int src = ei[e];
    const int dst = ei[n_edges + e];
    const int pos = atomicAdd(&g_off[src], 1);
    g_se[pos] = make_int2(src, dst);
    g_sp[pos] = reinterpret_cast<const float2*>(pseudo)[e];
}

// ---------------------------------------------------------------------------
// Edge kernel (sorted by src): 4 lanes/edge, 8 channels/lane.
// Per lane: 9 x LDG.128 (uint4 = 8 fp16) + 2 x red.v4.f32.
// ---------------------------------------------------------------------------
__global__ __launch_bounds__(256)
void edge_kernel(const __half* __restrict__ Y, float* __restrict__ agg,
                 int n_edges, int n_nodes)
{
    const int t   = blockIdx.x * 256 + threadIdx.x;
    const int e   = t >> 2;
    const int sub = t & 3;            // channels [8*sub, 8*sub+8)
    if (e >= n_edges) return;

    const int2   sd = g_se[e];
    const float2 p  = g_sp[e];
    if ((unsigned)sd.x >= (unsigned)n_nodes || (unsigned)sd.y >= (unsigned)n_nodes) return;

    const float q00 = 0.5f * (1.0f - p.x) * (1.0f - p.x);
    const float q01 = -p.x * p.x + p.x + 0.5f;
    const float q02 = 0.5f * p.x * p.x;
    const float q10 = 0.5f * (1.0f - p.y) * (1.0f - p.y);
    const float q11 = -p.y * p.y + p.y + 0.5f;
    const float q12 = 0.5f * p.y * p.y;

    const float bb[9] = { q10*q00, q10*q01, q10*q02,
                          q11*q00, q11*q01, q11*q02,
                          q12*q00, q12*q01, q12*q02 };

    const uint4* y = reinterpret_cast<const uint4*>(Y + (size_t)sd.x * CKOUT + sub * 8);

    float acc[8] = {0,0,0,0,0,0,0,0};
    #pragma unroll
    for (int k = 0; k < 9; k++) {
        const uint4 qv = y[k * 4];
        const float bk = bb[k];
        const float2 f0 = __half22float2(*reinterpret_cast<const __half2*>(&qv.x));
        const float2 f1 = __half22float2(*reinterpret_cast<const __half2*>(&qv.y));
        const float2 f2 = __half22float2(*reinterpret_cast<const __half2*>(&qv.z));
        const float2 f3 = __half22float2(*reinterpret_cast<const __half2*>(&qv.w));
        acc[0] += bk * f0.x; acc[1] += bk * f0.y;
        acc[2] += bk * f1.x; acc[3] += bk * f1.y;
        acc[4] += bk * f2.x; acc[5] += bk * f2.y;
        acc[6] += bk * f3.x; acc[7] += bk * f3.y;
    }

    float* dp = agg + (size_t)sd.y * 32 + sub * 8;
    asm volatile("red.global.add.v4.f32 [%0], {%1, %2, %3, %4};"
                 :: "l"(dp), "f"(acc[0]), "f"(acc[1]), "f"(acc[2]), "f"(acc[3]) : "memory");
    asm volatile("red.global.add.v4.f32 [%0], {%1, %2, %3, %4};"
                 :: "l"(dp + 4), "f"(acc[4]), "f"(acc[5]), "f"(acc[6]), "f"(acc[7]) : "memory");
}

__global__ void relu_kernel(float* __restrict__ d, int n)
{
    const int i = blockIdx.x * blockDim.x + threadIdx.x;
    if (i < n) d[i] = fmaxf(d[i], 0.0f);
}

// ---------------------------------------------------------------------------
extern "C" void kernel_launch(void* const* d_in, const int* in_sizes, int n_in,
                              void* d_out, int out_size)
{
    const float* x      = (const float*)d_in[0];
    const int*   ei     = (const int*)d_in[1];     // int64 in ref -> int32 in harness
    const float* pseudo = (const float*)d_in[2];
    const float* skip   = (const float*)d_in[3];
    const float* W1     = (const float*)d_in[4];
    const float* root1  = (const float*)d_in[5];
    const float* b1     = (const float*)d_in[6];
    const float* W2     = (const float*)d_in[7];
    const float* root2  = (const float*)d_in[8];
    const float* b2     = (const float*)d_in[9];

    const int N = in_sizes[0] / 64;
    const int E = in_sizes[1] / 2;
    float* out = (float*)d_out;

    __half* Y;
    float *agg1, *agg2;
    int* hist;
    cudaGetSymbolAddress((void**)&Y,    g_Y);
    cudaGetSymbolAddress((void**)&agg1, g_agg1);
    cudaGetSymbolAddress((void**)&agg2, g_agg2);
    cudaGetSymbolAddress((void**)&hist, g_hist);

    cudaFuncSetAttribute(gemm_mma<64, 0,  false, 64>,
                         cudaFuncAttributeMaxDynamicSharedMemorySize, SMEM_BYTES);
    cudaFuncSetAttribute(gemm_mma<32, 32, true,  64>,
                         cudaFuncAttributeMaxDynamicSharedMemorySize, SMEM_BYTES);
    cudaFuncSetAttribute(gemm_mma<32, 0,  true,  32>,
                         cudaFuncAttributeMaxDynamicSharedMemorySize, SMEM_BYTES);

    const int gemm_grid = 148;
    const int edge_grid = (E * 4 + 255) / 256;
    const int NB        = (N + 511) / 512;

    // ---- Sort edges by src (once; reused by all 3 edge passes).
    cudaMemsetAsync(hist, 0, (size_t)N * sizeof(int));
    hist_kernel<<<(E + 255) / 256, 256>>>(ei, E);
    scan1<<<NB, 512>>>(N);
    scan3<<<NB, 512>>>(N);
    scatter_kernel<<<(E + 255) / 256, 256>>>(ei, pseudo, E);

    // Layer 1: x[N,64] -> agg1
    gemm_mma<64, 0, false, 64><<<gemm_grid, 512, SMEM_BYTES>>>(x, nullptr, W1, root1, b1, Y, agg1, N);
    edge_kernel<<<edge_grid, 256>>>(Y, agg1, E, N);

    // Layer 2: concat(relu(agg1), skip)[N,64] -> agg2   (same W1/root1/b1)
    gemm_mma<32, 32, true, 64><<<gemm_grid, 512, SMEM_BYTES>>>(agg1, skip, W1, root1, b1, Y, agg2, N);
    edge_kernel<<<edge_grid, 256>>>(Y, agg2, E, N);

    // Layer 3: relu(agg2)[N,32] -> d_out  (K = 32 -> 2 k-steps)
    gemm_mma<32, 0, true, 32><<<gemm_grid, 512, SMEM_BYTES>>>(agg2, nullptr, W2, root2, b2, Y, out, N);
    edge_kernel<<<edge_grid, 256>>>(Y, out, E, N);

    relu_kernel<<<(N * 32 + 255) / 256, 256>>>(out, N * 32);
}

// round 15
// speedup vs baseline: 1.1900x; 1.0539x over previous
#include <cuda_runtime.h>
#include <cuda_fp16.h>
#include <cstdint>

// ---------------------------------------------------------------------------
// MeshUpConv: 3x SplineConv (kernel 3x3, degree 2, open spline) on GB300.
//
// R14 -> R15: combine R14's winning geometry/pipeline with R13's proven
// precision config: SINGLE fp16 MMA (W-lo dropped).
//   * MMA/warp-tile 160 -> 80, B-side LDSM halved, B staging halved,
//     smem 110.7KB -> 64.6KB. rel_err ~3.3e-4 (measured in R13, 3x margin).
//   * A-staging register double-buffer kept (R14 win).
// Edge pass (4 lanes/edge, uint4 fp16 gathers) + sort unchanged.
// ---------------------------------------------------------------------------

#define NMAX  50000
#define EMAX  400000
#define CKOUT 288          // K * C_OUT = 9 * 32
#define NCOLS 320          // 288 Y cols + 32 self cols

__device__ __half g_Y[(size_t)NMAX * CKOUT];
__device__ float  g_agg1[(size_t)NMAX * 32];
__device__ float  g_agg2[(size_t)NMAX * 32];

// sort scratch
__device__ int    g_hist[NMAX];
__device__ int    g_off[NMAX];
__device__ int    g_bsum[128];
__device__ int2   g_se[EMAX];     // sorted (src, dst)
__device__ float2 g_sp[EMAX];     // sorted pseudo

// ---- helpers --------------------------------------------------------------
__device__ __forceinline__ uint32_t pack_f16(float a, float b) {
    __half2 t = __floats2half2_rn(a, b);
    return *reinterpret_cast<uint32_t*>(&t);
}
__device__ __forceinline__ void mma_f16(float* c,
                                        uint32_t a0, uint32_t a1, uint32_t a2, uint32_t a3,
                                        uint32_t b0, uint32_t b1) {
    asm("mma.sync.aligned.m16n8k16.row.col.f32.f16.f16.f32 "
        "{%0,%1,%2,%3}, {%4,%5,%6,%7}, {%8,%9}, {%0,%1,%2,%3};"
        : "+f"(c[0]), "+f"(c[1]), "+f"(c[2]), "+f"(c[3])
        : "r"(a0), "r"(a1), "r"(a2), "r"(a3), "r"(b0), "r"(b1));
}
__device__ __forceinline__ void ldsm_x4(uint32_t& r0, uint32_t& r1,
                                        uint32_t& r2, uint32_t& r3, uint32_t a) {
    asm volatile("ldmatrix.sync.aligned.m8n8.x4.shared.b16 {%0,%1,%2,%3}, [%4];"
                 : "=r"(r0), "=r"(r1), "=r"(r2), "=r"(r3) : "r"(a));
}
__device__ __forceinline__ void ldsm_x2(uint32_t& r0, uint32_t& r1, uint32_t a) {
    asm volatile("ldmatrix.sync.aligned.m8n8.x2.shared.b16 {%0,%1}, [%2];"
                 : "=r"(r0), "=r"(r1) : "r"(a));
}
__device__ __forceinline__ uint32_t smem_addr(const void* p) {
    return (uint32_t)__cvta_generic_to_shared(p);
}

// SMEM layout. Stride 36 words: bank=(4q+r)%32 -> conflict-free fragments.
// A: 128 rows x 32 kpairs (fp16); B: 320 rows x 32 kpairs (fp16 single).
#define ASTR 36
#define SM_BIAS 0
#define SM_A    128
#define SM_B    (SM_A + 128 * ASTR * 4)          // 18560
#define SMEM_BYTES (SM_B + 320 * ASTR * 4)       // 64640

// ---------------------------------------------------------------------------
// mma.sync GEMM: per 128-node tile, D[128, 320] = A[128,64] @ Bw[64,320].
// 16 warps = 4(M) x 4(N); warp = 32 rows x 80 cols. fp16 in, fp32 accum.
// A staging double-buffered through registers (prefetch overlaps MMA loop).
// ---------------------------------------------------------------------------
template<int CA, int CB, bool RELU_A, int CIN_W>
__global__ __launch_bounds__(512)
void gemm_mma(const float* __restrict__ xa, const float* __restrict__ xb,
              const float* __restrict__ W, const float* __restrict__ root,
              const float* __restrict__ bias,
              __half* __restrict__ Y, float* __restrict__ agg, int n_nodes)
{
    extern __shared__ __align__(16) char smem[];
    uint32_t* Aa = reinterpret_cast<uint32_t*>(smem + SM_A);
    uint32_t* Bb = reinterpret_cast<uint32_t*>(smem + SM_B);
    float*    bs = reinterpret_cast<float*>(smem + SM_BIAS);

    const int tid    = threadIdx.x;
    const int wid    = tid >> 5;
    const int lane   = tid & 31;
    const int warp_m = wid >> 2;
    const int warp_n = wid & 3;
    constexpr int KSTEPS = CIN_W / 16;

    // ---- Stage B once per CTA (fp16; k padded to 64).
    for (int idx = tid; idx < NCOLS * 32; idx += 512) {
        const int r  = idx >> 5;
        const int kp = idx & 31;
        const int i0 = 2 * kp, i1 = i0 + 1;
        float v0 = 0.0f, v1 = 0.0f;
        if (i0 < CIN_W) {
            if (r < CKOUT) {
                const int kk = r >> 5, cc = r & 31;
                v0 = W[(kk * CIN_W + i0) * 32 + cc];
                v1 = W[(kk * CIN_W + i1) * 32 + cc];
            } else {
                v0 = root[i0 * 32 + (r - CKOUT)];
                v1 = root[i1 * 32 + (r - CKOUT)];
            }
        }
        Bb[r * ASTR + kp] = pack_f16(v0, v1);
    }
    if (tid < 32) bs[tid] = bias[tid];

    const uint32_t aoffw = (uint32_t)(warp_m * 32 + (lane & 15)) * ASTR + (lane >> 4) * 4;
    const uint32_t boffw = (uint32_t)(warp_n * 80 + (lane & 7)) * ASTR + ((lane >> 3) & 1) * 4;
    const uint32_t aA = smem_addr(Aa) + 4 * aoffw;
    const uint32_t bB = smem_addr(Bb) + 4 * boffw;

    const int ntiles = (n_nodes + 127) >> 7;

    // Per-thread A-staging slots: idx = tid + k*512, k = 0..7.
    auto load_tile = [&](int t, float2* pf) {
        const int n0 = t << 7;
        #pragma unroll
        for (int k = 0; k < 8; k++) {
            const int idx = tid + k * 512;
            const int row = idx >> 5;
            const int kp  = idx & 31;
            const int n   = n0 + row;
            const int i0  = 2 * kp;
            float2 v = make_float2(0.0f, 0.0f);
            if (n < n_nodes) {
                if (i0 < CA) {
                    v = *reinterpret_cast<const float2*>(xa + (size_t)n * CA + i0);
                } else if (CB > 0 && i0 < CA + CB) {
                    v = *reinterpret_cast<const float2*>(xb + (size_t)n * CB + (i0 - CA));
                }
            }
            pf[k] = v;
        }
    };

    int t = blockIdx.x;
    float2 pf[8];
    if (t < ntiles) load_tile(t, pf);
    __syncthreads();   // B ready (and A buffer free)

    for (; t < ntiles; t += gridDim.x) {
        const int n0 = t << 7;

        // ---- STS the prefetched tile (relu fused here).
        #pragma unroll
        for (int k = 0; k < 8; k++) {
            const int idx = tid + k * 512;
            const int row = idx >> 5;
            const int kp  = idx & 31;
            float v0 = pf[k].x, v1 = pf[k].y;
            if (RELU_A) {
                const int i0 = 2 * kp;
                if (i0 < CA) { v0 = fmaxf(v0, 0.0f); v1 = fmaxf(v1, 0.0f); }
            }
            Aa[row * ASTR + kp] = pack_f16(v0, v1);
        }
        __syncthreads();

        // ---- Prefetch next tile (latency hidden under the MMA loop).
        const int tn = t + gridDim.x;
        if (tn < ntiles) load_tile(tn, pf);

        float acc[2][10][4];
        #pragma unroll
        for (int mt = 0; mt < 2; mt++)
            #pragma unroll
            for (int nt = 0; nt < 10; nt++)
                #pragma unroll
                for (int j = 0; j < 4; j++) acc[mt][nt][j] = 0.0f;

        #pragma unroll
        for (int ks = 0; ks < KSTEPS; ks++) {
            const uint32_t ko = 4u * ks * 8;
            uint32_t a_[2][4];
            #pragma unroll
            for (int mt = 0; mt < 2; mt++)
                ldsm_x4(a_[mt][0], a_[mt][1], a_[mt][2], a_[mt][3],
                        aA + 4u * mt * 16 * ASTR + ko);
            #pragma unroll
            for (int nt = 0; nt < 10; nt++) {
                uint32_t b0, b1;
                ldsm_x2(b0, b1, bB + 4u * nt * 8 * ASTR + ko);
                #pragma unroll
                for (int mt = 0; mt < 2; mt++)
                    mma_f16(acc[mt][nt], a_[mt][0], a_[mt][1], a_[mt][2], a_[mt][3], b0, b1);
            }
        }

        // ---- Epilogue: Y cols -> fp16 (half2 store); self cols -> fp32 agg.
        const int q   = lane >> 2;
        const int lkp = lane & 3;
        #pragma unroll
        for (int mt = 0; mt < 2; mt++) {
            const int r0 = n0 + warp_m * 32 + mt * 16 + q;
            const int r1 = r0 + 8;
            #pragma unroll
            for (int nt = 0; nt < 10; nt++) {
                const int col0 = warp_n * 80 + nt * 8 + 2 * lkp;
                if (col0 < CKOUT) {
                    if (r0 < n_nodes)
                        *reinterpret_cast<__half2*>(Y + (size_t)r0 * CKOUT + col0)
                            = __floats2half2_rn(acc[mt][nt][0], acc[mt][nt][1]);
                    if (r1 < n_nodes)
                        *reinterpret_cast<__half2*>(Y + (size_t)r1 * CKOUT + col0)
                            = __floats2half2_rn(acc[mt][nt][2], acc[mt][nt][3]);
                } else {
                    const int a = col0 - CKOUT;
                    const float b0v = bs[a], b1v = bs[a + 1];
                    if (r0 < n_nodes)
                        *reinterpret_cast<float2*>(agg + (size_t)r0 * 32 + a)
                            = make_float2(acc[mt][nt][0] + b0v, acc[mt][nt][1] + b1v);
                    if (r1 < n_nodes)
                        *reinterpret_cast<float2*>(agg + (size_t)r1 * 32 + a)
                            = make_float2(acc[mt][nt][2] + b0v, acc[mt][nt][3] + b1v);
                }
            }
        }
        __syncthreads();   // done reading Aa before next STS
    }
}

// ---------------------------------------------------------------------------
// Counting sort of edges by src (once per launch, reused by 3 edge passes).
// ---------------------------------------------------------------------------
__global__ void hist_kernel(const int* __restrict__ ei, int n_edges) {
    const int e = blockIdx.x * blockDim.x + threadIdx.x;
    if (e < n_edges) atomicAdd(&g_hist[ei[e]], 1);
}
__global__ void scan1(int n) {
    __shared__ int s[512];
    const int tid = threadIdx.x;
    const int b   = blockIdx.x * 512 + tid;
    const int v   = (b < n) ? g_hist[b] : 0;
    s[tid] = v;
    __syncthreads();
    #pragma unroll
    for (int off = 1; off < 512; off <<= 1) {
        int t = (tid >= off) ? s[tid - off] : 0;
        __syncthreads();
        s[tid] += t;
        __syncthreads();
    }
    if (b < n) g_off[b] = s[tid] - v;
    if (tid == 511) g_bsum[blockIdx.x] = s[511];
}
__global__ void scan3(int n) {
    __shared__ int pref;
    const int bid = blockIdx.x;
    if (threadIdx.x < 32) {
        int s = 0;
        for (int i = threadIdx.x; i < bid; i += 32) s += g_bsum[i];
        #pragma unroll
        for (int o = 16; o; o >>= 1) s += __shfl_down_sync(0xffffffffu, s, o);
        if (threadIdx.x == 0) pref = s;
    }
    __syncthreads();
    const int b = bid * 512 + threadIdx.x;
    if (b < n) g_off[b] += pref;
}
__global__ void scatter_kernel(const int* __restrict__ ei,
                               const float* __restrict__ pseudo, int n_edges) {
    const int e = blockIdx.x * blockDim.x + threadIdx.x;
    if (e >= n_edges) return;
    const int src = ei[e];
    const int dst = ei[n_edges + e];
    const int pos = atomicAdd(&g_off[src], 1);
    g_se[pos] = make_int2(src, dst);
    g_sp[pos] = reinterpret_cast<const float2*>(pseudo)[e];
}

// ---------------------------------------------------------------------------
// Edge kernel (sorted by src): 4 lanes/edge, 8 channels/lane.
// Per lane: 9 x LDG.128 (uint4 = 8 fp16) + 2 x red.v4.f32.
// ---------------------------------------------------------------------------
__global__ __launch_bounds__(256)
void edge_kernel(const __half* __restrict__ Y, float* __restrict__ agg,
                 int n_edges, int n_nodes)
{
    const int t   = blockIdx.x * 256 + threadIdx.x;
    const int e   = t >> 2;
    const int sub = t & 3;            // channels [8*sub, 8*sub+8)
    if (e >= n_edges) return;

    const int2   sd = g_se[e];
    const float2 p  = g_sp[e];
    if ((unsigned)sd.x >= (unsigned)n_nodes || (unsigned)sd.y >= (unsigned)n_nodes) return;

    const float q00 = 0.5f * (1.0f - p.x) * (1.0f - p.x);
    const float q01 = -p.x * p.x + p.x + 0.5f;
    const float q02 = 0.5f * p.x * p.x;
    const float q10 = 0.5f * (1.0f - p.y) * (1.0f - p.y);
    const float q11 = -p.y * p.y + p.y + 0.5f;
    const float q12 = 0.5f * p.y * p.y;

    const float bb[9] = { q10*q00, q10*q01, q10*q02,
                          q11*q00, q11*q01, q11*q02,
                          q12*q00, q12*q01, q12*q02 };

    const uint4* y = reinterpret_cast<const uint4*>(Y + (size_t)sd.x * CKOUT + sub * 8);

    float acc[8] = {0,0,0,0,0,0,0,0};
    #pragma unroll
    for (int k = 0; k < 9; k++) {
        const uint4 qv = y[k * 4];
        const float bk = bb[k];
        const float2 f0 = __half22float2(*reinterpret_cast<const __half2*>(&qv.x));
        const float2 f1 = __half22float2(*reinterpret_cast<const __half2*>(&qv.y));
        const float2 f2 = __half22float2(*reinterpret_cast<const __half2*>(&qv.z));
        const float2 f3 = __half22float2(*reinterpret_cast<const __half2*>(&qv.w));
        acc[0] += bk * f0.x; acc[1] += bk * f0.y;
        acc[2] += bk * f1.x; acc[3] += bk * f1.y;
        acc[4] += bk * f2.x; acc[5] += bk * f2.y;
        acc[6] += bk * f3.x; acc[7] += bk * f3.y;
    }

    float* dp = agg + (size_t)sd.y * 32 + sub * 8;
    asm volatile("red.global.add.v4.f32 [%0], {%1, %2, %3, %4};"
                 :: "l"(dp), "f"(acc[0]), "f"(acc[1]), "f"(acc[2]), "f"(acc[3]) : "memory");
    asm volatile("red.global.add.v4.f32 [%0], {%1, %2, %3, %4};"
                 :: "l"(dp + 4), "f"(acc[4]), "f"(acc[5]), "f"(acc[6]), "f"(acc[7]) : "memory");
}

__global__ void relu_kernel(float* __restrict__ d, int n)
{
    const int i = blockIdx.x * blockDim.x + threadIdx.x;
    if (i < n) d[i] = fmaxf(d[i], 0.0f);
}

// ---------------------------------------------------------------------------
extern "C" void kernel_launch(void* const* d_in, const int* in_sizes, int n_in,
                              void* d_out, int out_size)
{
    const float* x      = (const float*)d_in[0];
    const int*   ei     = (const int*)d_in[1];     // int64 in ref -> int32 in harness
    const float* pseudo = (const float*)d_in[2];
    const float* skip   = (const float*)d_in[3];
    const float* W1     = (const float*)d_in[4];
    const float* root1  = (const float*)d_in[5];
    const float* b1     = (const float*)d_in[6];
    const float* W2     = (const float*)d_in[7];
    const float* root2  = (const float*)d_in[8];
    const float* b2     = (const float*)d_in[9];

    const int N = in_sizes[0] / 64;
    const int E = in_sizes[1] / 2;
    float* out = (float*)d_out;

    __half* Y;
    float *agg1, *agg2;
    int* hist;
    cudaGetSymbolAddress((void**)&Y,    g_Y);
    cudaGetSymbolAddress((void**)&agg1, g_agg1);
    cudaGetSymbolAddress((void**)&agg2, g_agg2);
    cudaGetSymbolAddress((void**)&hist, g_hist);

    cudaFuncSetAttribute(gemm_mma<64, 0,  false, 64>,
                         cudaFuncAttributeMaxDynamicSharedMemorySize, SMEM_BYTES);
    cudaFuncSetAttribute(gemm_mma<32, 32, true,  64>,
                         cudaFuncAttributeMaxDynamicSharedMemorySize, SMEM_BYTES);
    cudaFuncSetAttribute(gemm_mma<32, 0,  true,  32>,
                         cudaFuncAttributeMaxDynamicSharedMemorySize, SMEM_BYTES);

    const int gemm_grid = 148;
    const int edge_grid = (E * 4 + 255) / 256;
    const int NB        = (N + 511) / 512;

    // ---- Sort edges by src (once; reused by all 3 edge passes).
    cudaMemsetAsync(hist, 0, (size_t)N * sizeof(int));
    hist_kernel<<<(E + 255) / 256, 256>>>(ei, E);
    scan1<<<NB, 512>>>(N);
    scan3<<<NB, 512>>>(N);
    scatter_kernel<<<(E + 255) / 256, 256>>>(ei, pseudo, E);

    // Layer 1: x[N,64] -> agg1
    gemm_mma<64, 0, false, 64><<<gemm_grid, 512, SMEM_BYTES>>>(x, nullptr, W1, root1, b1, Y, agg1, N);
    edge_kernel<<<edge_grid, 256>>>(Y, agg1, E, N);

    // Layer 2: concat(relu(agg1), skip)[N,64] -> agg2   (same W1/root1/b1)
    gemm_mma<32, 32, true, 64><<<gemm_grid, 512, SMEM_BYTES>>>(agg1, skip, W1, root1, b1, Y, agg2, N);
    edge_kernel<<<edge_grid, 256>>>(Y, agg2, E, N);

    // Layer 3: relu(agg2)[N,32] -> d_out  (K = 32 -> 2 k-steps)
    gemm_mma<32, 0, true, 32><<<gemm_grid, 512, SMEM_BYTES>>>(agg2, nullptr, W2, root2, b2, Y, out, N);
    edge_kernel<<<edge_grid, 256>>>(Y, out, E, N);

    relu_kernel<<<(N * 32 + 255) / 256, 256>>>(out, N * 32);
}

// round 16
// speedup vs baseline: 1.2598x; 1.0587x over previous
#include <cuda_runtime.h>
#include <cuda_fp16.h>
#include <cstdint>

// ---------------------------------------------------------------------------
// MeshUpConv: 3x SplineConv (kernel 3x3, degree 2, open spline) on GB300.
//
// R15 -> R16:
//   * Sort chain moved to a second stream, fork/join via events inside graph
//     capture -> overlaps with layer-1 GEMM (~20us hidden).
//   * Edge data packed: (src,dst,px,py) in one 16B struct -> scatter does a
//     single STG.128, edge kernel a single broadcast LDG.128.
// GEMM (fp16 single MMA, A-prefetch pipeline) + edge pass unchanged from R15.
// ---------------------------------------------------------------------------

#define NMAX  50000
#define EMAX  400000
#define CKOUT 288          // K * C_OUT = 9 * 32
#define NCOLS 320          // 288 Y cols + 32 self cols

__device__ __half g_Y[(size_t)NMAX * CKOUT];
__device__ float  g_agg1[(size_t)NMAX * 32];
__device__ float  g_agg2[(size_t)NMAX * 32];

// sort scratch
struct __align__(16) Edge { int src; int dst; float px; float py; };
__device__ int  g_hist[NMAX];
__device__ int  g_off[NMAX];
__device__ int  g_bsum[128];
__device__ Edge g_ed[EMAX];       // sorted packed edges

// ---- helpers --------------------------------------------------------------
__device__ __forceinline__ uint32_t pack_f16(float a, float b) {
    __half2 t = __floats2half2_rn(a, b);
    return *reinterpret_cast<uint32_t*>(&t);
}
__device__ __forceinline__ void mma_f16(float* c,
                                        uint32_t a0, uint32_t a1, uint32_t a2, uint32_t a3,
                                        uint32_t b0, uint32_t b1) {
    asm("mma.sync.aligned.m16n8k16.row.col.f32.f16.f16.f32 "
        "{%0,%1,%2,%3}, {%4,%5,%6,%7}, {%8,%9}, {%0,%1,%2,%3};"
        : "+f"(c[0]), "+f"(c[1]), "+f"(c[2]), "+f"(c[3])
        : "r"(a0), "r"(a1), "r"(a2), "r"(a3), "r"(b0), "r"(b1));
}
__device__ __forceinline__ void ldsm_x4(uint32_t& r0, uint32_t& r1,
                                        uint32_t& r2, uint32_t& r3, uint32_t a) {
    asm volatile("ldmatrix.sync.aligned.m8n8.x4.shared.b16 {%0,%1,%2,%3}, [%4];"
                 : "=r"(r0), "=r"(r1), "=r"(r2), "=r"(r3) : "r"(a));
}
__device__ __forceinline__ void ldsm_x2(uint32_t& r0, uint32_t& r1, uint32_t a) {
    asm volatile("ldmatrix.sync.aligned.m8n8.x2.shared.b16 {%0,%1}, [%2];"
                 : "=r"(r0), "=r"(r1) : "r"(a));
}
__device__ __forceinline__ uint32_t smem_addr(const void* p) {
    return (uint32_t)__cvta_generic_to_shared(p);
}

// SMEM layout. Stride 36 words: bank=(4q+r)%32 -> conflict-free fragments.
#define ASTR 36
#define SM_BIAS 0
#define SM_A    128
#define SM_B    (SM_A + 128 * ASTR * 4)          // 18560
#define SMEM_BYTES (SM_B + 320 * ASTR * 4)       // 64640

// ---------------------------------------------------------------------------
// mma.sync GEMM: per 128-node tile, D[128, 320] = A[128,64] @ Bw[64,320].
// 16 warps = 4(M) x 4(N); warp = 32 rows x 80 cols. fp16 in, fp32 accum.
// A staging double-buffered through registers (prefetch overlaps MMA loop).
// ---------------------------------------------------------------------------
template<int CA, int CB, bool RELU_A, int CIN_W>
__global__ __launch_bounds__(512)
void gemm_mma(const float* __restrict__ xa, const float* __restrict__ xb,
              const float* __restrict__ W, const float* __restrict__ root,
              const float* __restrict__ bias,
              __half* __restrict__ Y, float* __restrict__ agg, int n_nodes)
{
    extern __shared__ __align__(16) char smem[];
    uint32_t* Aa = reinterpret_cast<uint32_t*>(smem + SM_A);
    uint32_t* Bb = reinterpret_cast<uint32_t*>(smem + SM_B);
    float*    bs = reinterpret_cast<float*>(smem + SM_BIAS);

    const int tid    = threadIdx.x;
    const int wid    = tid >> 5;
    const int lane   = tid & 31;
    const int warp_m = wid >> 2;
    const int warp_n = wid & 3;
    constexpr int KSTEPS = CIN_W / 16;

    // ---- Stage B once per CTA (fp16; k padded to 64).
    for (int idx = tid; idx < NCOLS * 32; idx += 512) {
        const int r  = idx >> 5;
        const int kp = idx & 31;
        const int i0 = 2 * kp, i1 = i0 + 1;
        float v0 = 0.0f, v1 = 0.0f;
        if (i0 < CIN_W) {
            if (r < CKOUT) {
                const int kk = r >> 5, cc = r & 31;
                v0 = W[(kk * CIN_W + i0) * 32 + cc];
                v1 = W[(kk * CIN_W + i1) * 32 + cc];
            } else {
                v0 = root[i0 * 32 + (r - CKOUT)];
                v1 = root[i1 * 32 + (r - CKOUT)];
            }
        }
        Bb[r * ASTR + kp] = pack_f16(v0, v1);
    }
    if (tid < 32) bs[tid] = bias[tid];

    const uint32_t aoffw = (uint32_t)(warp_m * 32 + (lane & 15)) * ASTR + (lane >> 4) * 4;
    const uint32_t boffw = (uint32_t)(warp_n * 80 + (lane & 7)) * ASTR + ((lane >> 3) & 1) * 4;
    const uint32_t aA = smem_addr(Aa) + 4 * aoffw;
    const uint32_t bB = smem_addr(Bb) + 4 * boffw;

    const int ntiles = (n_nodes + 127) >> 7;

    // Per-thread A-staging slots: idx = tid + k*512, k = 0..7.
    auto load_tile = [&](int t, float2* pf) {
        const int n0 = t << 7;
        #pragma unroll
        for (int k = 0; k < 8; k++) {
            const int idx = tid + k * 512;
            const int row = idx >> 5;
            const int kp  = idx & 31;
            const int n   = n0 + row;
            const int i0  = 2 * kp;
            float2 v = make_float2(0.0f, 0.0f);
            if (n < n_nodes) {
                if (i0 < CA) {
                    v = *reinterpret_cast<const float2*>(xa + (size_t)n * CA + i0);
                } else if (CB > 0 && i0 < CA + CB) {
                    v = *reinterpret_cast<const float2*>(xb + (size_t)n * CB + (i0 - CA));
                }
            }
            pf[k] = v;
        }
    };

    int t = blockIdx.x;
    float2 pf[8];
    if (t < ntiles) load_tile(t, pf);
    __syncthreads();   // B ready (and A buffer free)

    for (; t < ntiles; t += gridDim.x) {
        const int n0 = t << 7;

        // ---- STS the prefetched tile (relu fused here).
        #pragma unroll
        for (int k = 0; k < 8; k++) {
            const int idx = tid + k * 512;
            const int row = idx >> 5;
            const int kp  = idx & 31;
            float v0 = pf[k].x, v1 = pf[k].y;
            if (RELU_A) {
                const int i0 = 2 * kp;
                if (i0 < CA) { v0 = fmaxf(v0, 0.0f); v1 = fmaxf(v1, 0.0f); }
            }
            Aa[row * ASTR + kp] = pack_f16(v0, v1);
        }
        __syncthreads();

        // ---- Prefetch next tile (latency hidden under the MMA loop).
        const int tn = t + gridDim.x;
        if (tn < ntiles) load_tile(tn, pf);

        float acc[2][10][4];
        #pragma unroll
        for (int mt = 0; mt < 2; mt++)
            #pragma unroll
            for (int nt = 0; nt < 10; nt++)
                #pragma unroll
                for (int j = 0; j < 4; j++) acc[mt][nt][j] = 0.0f;

        #pragma unroll
        for (int ks = 0; ks < KSTEPS; ks++) {
            const uint32_t ko = 4u * ks * 8;
            uint32_t a_[2][4];
            #pragma unroll
            for (int mt = 0; mt < 2; mt++)
                ldsm_x4(a_[mt][0], a_[mt][1], a_[mt][2], a_[mt][3],
                        aA + 4u * mt * 16 * ASTR + ko);
            #pragma unroll
            for (int nt = 0; nt < 10; nt++) {
                uint32_t b0, b1;
                ldsm_x2(b0, b1, bB + 4u * nt * 8 * ASTR + ko);
                #pragma unroll
                for (int mt = 0; mt < 2; mt++)
                    mma_f16(acc[mt][nt], a_[mt][0], a_[mt][1], a_[mt][2], a_[mt][3], b0, b1);
            }
        }

        // ---- Epilogue: Y cols -> fp16 (half2 store); self cols -> fp32 agg.
        const int q   = lane >> 2;
        const int lkp = lane & 3;
        #pragma unroll
        for (int mt = 0; mt < 2; mt++) {
            const int r0 = n0 + warp_m * 32 + mt * 16 + q;
            const int r1 = r0 + 8;
            #pragma unroll
            for (int nt = 0; nt < 10; nt++) {
                const int col0 = warp_n * 80 + nt * 8 + 2 * lkp;
                if (col0 < CKOUT) {
                    if (r0 < n_nodes)
                        *reinterpret_cast<__half2*>(Y + (size_t)r0 * CKOUT + col0)
                            = __floats2half2_rn(acc[mt][nt][0], acc[mt][nt][1]);
                    if (r1 < n_nodes)
                        *reinterpret_cast<__half2*>(Y + (size_t)r1 * CKOUT + col0)
                            = __floats2half2_rn(acc[mt][nt][2], acc[mt][nt][3]);
                } else {
                    const int a = col0 - CKOUT;
                    const float b0v = bs[a], b1v = bs[a + 1];
                    if (r0 < n_nodes)
                        *reinterpret_cast<float2*>(agg + (size_t)r0 * 32 + a)
                            = make_float2(acc[mt][nt][0] + b0v, acc[mt][nt][1] + b1v);
                    if (r1 < n_nodes)
                        *reinterpret_cast<float2*>(agg + (size_t)r1 * 32 + a)
                            = make_float2(acc[mt][nt][2] + b0v, acc[mt][nt][3] + b1v);
                }
            }
        }
        __syncthreads();   // done reading Aa before next STS
    }
}

// ---------------------------------------------------------------------------
// Counting sort of edges by src (overlapped with layer-1 GEMM on stream 2).
// ---------------------------------------------------------------------------
__global__ void hist_kernel(const int* __restrict__ ei, int n_edges) {
    const int e = blockIdx.x * blockDim.x + threadIdx.x;
    if (e < n_edges) atomicAdd(&g_hist[ei[e]], 1);
}
__global__ void scan1(int n) {
    __shared__ int s[512];
    const int tid = threadIdx.x;
    const int b   = blockIdx.x * 512 + tid;
    const int v   = (b < n) ? g_hist[b] : 0;
    s[tid] = v;
    __syncthreads();
    #pragma unroll
    for (int off = 1; off < 512; off <<= 1) {
        int t = (tid >= off) ? s[tid - off] : 0;
        __syncthreads();
        s[tid] += t;
        __syncthreads();
    }
    if (b < n) g_off[b] = s[tid] - v;
    if (tid == 511) g_bsum[blockIdx.x] = s[511];
}
__global__ void scan3(int n) {
    __shared__ int pref;
    const int bid = blockIdx.x;
    if (threadIdx.x < 32) {
        int s = 0;
        for (int i = threadIdx.x; i < bid; i += 32) s += g_bsum[i];
        #pragma unroll
        for (int o = 16; o; o >>= 1) s += __shfl_down_sync(0xffffffffu, s, o);
        if (threadIdx.x == 0) pref = s;
    }
    __syncthreads();
    const int b = bid * 512 + threadIdx.x;
    if (b < n) g_off[b] += pref;
}
__global__ void scatter_kernel(const int* __restrict__ ei,
                               const float* __restrict__ pseudo, int n_edges) {
    const int e = blockIdx.x * blockDim.x + threadIdx.x;
    if (e >= n_edges) return;
    const int src = ei[e];
    const int dst = ei[n_edges + e];
    const float2 p = reinterpret_cast<const float2*>(pseudo)[e];
    const int pos = atomicAdd(&g_off[src], 1);
    Edge ed; ed.src = src; ed.dst = dst; ed.px = p.x; ed.py = p.y;
    g_ed[pos] = ed;                    // single STG.128
}

// ---------------------------------------------------------------------------
// Edge kernel (sorted by src): 4 lanes/edge, 8 channels/lane.
// Per lane: 1 broadcast LDG.128 (edge) + 9 LDG.128 (Y) + 2 red.v4.f32.
// ---------------------------------------------------------------------------
__global__ __launch_bounds__(256)
void edge_kernel(const __half* __restrict__ Y, float* __restrict__ agg,
                 int n_edges, int n_nodes)
{
    const int t   = blockIdx.x * 256 + threadIdx.x;
    const int e   = t >> 2;
    const int sub = t & 3;            // channels [8*sub, 8*sub+8)
    if (e >= n_edges) return;

    const Edge ed = g_ed[e];
    if ((unsigned)ed.src >= (unsigned)n_nodes || (unsigned)ed.dst >= (unsigned)n_nodes) return;

    const float q00 = 0.5f * (1.0f - ed.px) * (1.0f - ed.px);
    const float q01 = -ed.px * ed.px + ed.px + 0.5f;
    const float q02 = 0.5f * ed.px * ed.px;
    const float q10 = 0.5f * (1.0f - ed.py) * (1.0f - ed.py);
    const float q11 = -ed.py * ed.py + ed.py + 0.5f;
    const float q12 = 0.5f * ed.py * ed.py;

    const float bb[9] = { q10*q00, q10*q01, q10*q02,
                          q11*q00, q11*q01, q11*q02,
                          q12*q00, q12*q01, q12*q02 };

    const uint4* y = reinterpret_cast<const uint4*>(Y + (size_t)ed.src * CKOUT + sub * 8);

    float acc[8] = {0,0,0,0,0,0,0,0};
    #pragma unroll
    for (int k = 0; k < 9; k++) {
        const uint4 qv = y[k * 4];
        const float bk = bb[k];
        const float2 f0 = __half22float2(*reinterpret_cast<const __half2*>(&qv.x));
        const float2 f1 = __half22float2(*reinterpret_cast<const __half2*>(&qv.y));
        const float2 f2 = __half22float2(*reinterpret_cast<const __half2*>(&qv.z));
        const float2 f3 = __half22float2(*reinterpret_cast<const __half2*>(&qv.w));
        acc[0] += bk * f0.x; acc[1] += bk * f0.y;
        acc[2] += bk * f1.x; acc[3] += bk * f1.y;
        acc[4] += bk * f2.x; acc[5] += bk * f2.y;
        acc[6] += bk * f3.x; acc[7] += bk * f3.y;
    }

    float* dp = agg + (size_t)ed.dst * 32 + sub * 8;
    asm volatile("red.global.add.v4.f32 [%0], {%1, %2, %3, %4};"
                 :: "l"(dp), "f"(acc[0]), "f"(acc[1]), "f"(acc[2]), "f"(acc[3]) : "memory");
    asm volatile("red.global.add.v4.f32 [%0], {%1, %2, %3, %4};"
                 :: "l"(dp + 4), "f"(acc[4]), "f"(acc[5]), "f"(acc[6]), "f"(acc[7]) : "memory");
}

__global__ void relu_kernel(float* __restrict__ d, int n)
{
    const int i = blockIdx.x * blockDim.x + threadIdx.x;
    if (i < n) d[i] = fmaxf(d[i], 0.0f);
}

// ---------------------------------------------------------------------------
extern "C" void kernel_launch(void* const* d_in, const int* in_sizes, int n_in,
                              void* d_out, int out_size)
{
    const float* x      = (const float*)d_in[0];
    const int*   ei     = (const int*)d_in[1];     // int64 in ref -> int32 in harness
    const float* pseudo = (const float*)d_in[2];
    const float* skip   = (const float*)d_in[3];
    const float* W1     = (const float*)d_in[4];
    const float* root1  = (const float*)d_in[5];
    const float* b1     = (const float*)d_in[6];
    const float* W2     = (const float*)d_in[7];
    const float* root2  = (const float*)d_in[8];
    const float* b2     = (const float*)d_in[9];

    const int N = in_sizes[0] / 64;
    const int E = in_sizes[1] / 2;
    float* out = (float*)d_out;

    __half* Y;
    float *agg1, *agg2;
    int* hist;
    cudaGetSymbolAddress((void**)&Y,    g_Y);
    cudaGetSymbolAddress((void**)&agg1, g_agg1);
    cudaGetSymbolAddress((void**)&agg2, g_agg2);
    cudaGetSymbolAddress((void**)&hist, g_hist);

    cudaFuncSetAttribute(gemm_mma<64, 0,  false, 64>,
                         cudaFuncAttributeMaxDynamicSharedMemorySize, SMEM_BYTES);
    cudaFuncSetAttribute(gemm_mma<32, 32, true,  64>,
                         cudaFuncAttributeMaxDynamicSharedMemorySize, SMEM_BYTES);
    cudaFuncSetAttribute(gemm_mma<32, 0,  true,  32>,
                         cudaFuncAttributeMaxDynamicSharedMemorySize, SMEM_BYTES);

    const int gemm_grid = 148;
    const int edge_grid = (E * 4 + 255) / 256;
    const int NB        = (N + 511) / 512;

    // ---- Fork: sort chain on stream 2, overlapped with layer-1 GEMM.
    // (Created per call; kernel_launch runs only for correctness + capture,
    //  so at most a few stream/event objects exist. No device-memory allocs.)
    cudaStream_t s2;
    cudaStreamCreateWithFlags(&s2, cudaStreamNonBlocking);
    cudaEvent_t evFork, evJoin;
    cudaEventCreateWithFlags(&evFork, cudaEventDisableTiming);
    cudaEventCreateWithFlags(&evJoin, cudaEventDisableTiming);

    cudaEventRecord(evFork, 0);
    cudaStreamWaitEvent(s2, evFork, 0);

    cudaMemsetAsync(hist, 0, (size_t)N * sizeof(int), s2);
    hist_kernel<<<(E + 255) / 256, 256, 0, s2>>>(ei, E);
    scan1<<<NB, 512, 0, s2>>>(N);
    scan3<<<NB, 512, 0, s2>>>(N);
    scatter_kernel<<<(E + 255) / 256, 256, 0, s2>>>(ei, pseudo, E);
    cudaEventRecord(evJoin, s2);

    // Layer 1 GEMM runs concurrently on the main stream.
    gemm_mma<64, 0, false, 64><<<gemm_grid, 512, SMEM_BYTES>>>(x, nullptr, W1, root1, b1, Y, agg1, N);

    cudaStreamWaitEvent(0, evJoin, 0);   // join: edge1 needs sorted edges
    edge_kernel<<<edge_grid, 256>>>(Y, agg1, E, N);

    // Layer 2: concat(relu(agg1), skip)[N,64] -> agg2   (same W1/root1/b1)
    gemm_mma<32, 32, true, 64><<<gemm_grid, 512, SMEM_BYTES>>>(agg1, skip, W1, root1, b1, Y, agg2, N);
    edge_kernel<<<edge_grid, 256>>>(Y, agg2, E, N);

    // Layer 3: relu(agg2)[N,32] -> d_out  (K = 32 -> 2 k-steps)
    gemm_mma<32, 0, true, 32><<<gemm_grid, 512, SMEM_BYTES>>>(agg2, nullptr, W2, root2, b2, Y, out, N);
    edge_kernel<<<edge_grid, 256>>>(Y, out, E, N);

    relu_kernel<<<(N * 32 + 255) / 256, 256>>>(out, N * 32);
}